// round 12
// baseline (speedup 1.0000x reference)
#include <cuda_runtime.h>
#include <cuda_bf16.h>
#include <cstdint>

// Problem constants
#define BATCH    16384
#define IN_SIZE  448
#define OUT_SIZE 448
#define W_TOT    14336
#define NE       64
#define NB       64
#define NTHREADS 512
#define PTHREADS 256
#define NHB      (BATCH / PTHREADS)   // 64
#define MAX_TILES 320
#define GRID_COMPUTE 296

// B (W^T) image layout per element, padded row strides (odd*16 -> conflict-free)
#define B0_STR 208
#define B1_STR 144
#define B2_STR 80
#define OFF_B0H 0
#define OFF_B0L 19968
#define OFF_B1H 39936
#define OFF_B1L 49152
#define OFF_B2H 58368
#define OFF_B2L 60928
#define IMG_BYTES 63488

__device__ unsigned char g_Wimg[(size_t)NE * IMG_BYTES];
__device__ int g_hist[NHB][NE];
__device__ int g_perm[BATCH];
__device__ int g_ntiles;
__device__ int g_tile_ctr;
__device__ int g_tile_e[MAX_TILES];
__device__ int g_tile_r0[MAX_TILES];
__device__ int g_tile_R[MAX_TILES];

__device__ __forceinline__ int get_idx(const void* p, int b, int is64) {
    if (is64) return (int)((const long long*)p)[b];
    return ((const int*)p)[b];
}
__device__ __forceinline__ int detect_is64(const void* idxp, int tid, int* s_flag) {
    if (tid < 32) {
        long long v = ((const long long*)idxp)[tid];
        unsigned ok = __ballot_sync(0xFFFFFFFFu, v >= 0 && v < 64);
        if (tid == 0) *s_flag = (ok == 0xFFFFFFFFu) ? 1 : 0;
    }
    __syncthreads();
    return *s_flag;
}
__device__ __forceinline__ uint32_t pk2(float a, float b, float* la, float* lb) {
    __nv_bfloat16 ha = __float2bfloat16_rn(a);
    __nv_bfloat16 hb = __float2bfloat16_rn(b);
    *la = a - __bfloat162float(ha);
    *lb = b - __bfloat162float(hb);
    uint16_t ua, ub;
    memcpy(&ua, &ha, 2); memcpy(&ub, &hb, 2);
    return (uint32_t)ua | ((uint32_t)ub << 16);
}
__device__ __forceinline__ uint32_t pk2lo(float la, float lb) {
    __nv_bfloat16 a = __float2bfloat16_rn(la);
    __nv_bfloat16 b = __float2bfloat16_rn(lb);
    uint16_t ua, ub;
    memcpy(&ua, &a, 2); memcpy(&ub, &b, 2);
    return (uint32_t)ua | ((uint32_t)ub << 16);
}

// ---------------------------------------------------------------------------
// K0: fused W-image build (blocks 0..63) + histogram (blocks 64..127)
// ---------------------------------------------------------------------------
__global__ void prep_kernel(const float* __restrict__ W, const void* idxp) {
    int tid = threadIdx.x;
    if (blockIdx.x < NE) {
        int e = blockIdx.x;
        const float* We = W + (size_t)e * W_TOT;
        unsigned char* img = g_Wimg + (size_t)e * IMG_BYTES;
        for (int i = tid; i < 96 * 48; i += PTHREADS) {
            int o = i / 48, k = 2 * (i - 48 * (i / 48));
            float la, lb;
            uint32_t h = pk2(We[k * 96 + o], We[(k + 1) * 96 + o], &la, &lb);
            *(uint32_t*)(img + OFF_B0H + o * B0_STR + 2 * k) = h;
            *(uint32_t*)(img + OFF_B0L + o * B0_STR + 2 * k) = pk2lo(la, lb);
        }
        for (int i = tid; i < 64 * 32; i += PTHREADS) {
            int o = i >> 5, k = (i & 31) * 2;
            float la, lb;
            uint32_t h = pk2(We[9216 + k * 64 + o], We[9216 + (k + 1) * 64 + o], &la, &lb);
            *(uint32_t*)(img + OFF_B1H + o * B1_STR + 2 * k) = h;
            *(uint32_t*)(img + OFF_B1L + o * B1_STR + 2 * k) = pk2lo(la, lb);
        }
        for (int i = tid; i < 32 * 16; i += PTHREADS) {
            int o = i >> 4, k = (i & 15) * 2;
            float la, lb;
            uint32_t h = pk2(We[13312 + k * 32 + o], We[13312 + (k + 1) * 32 + o], &la, &lb);
            *(uint32_t*)(img + OFF_B2H + o * B2_STR + 2 * k) = h;
            *(uint32_t*)(img + OFF_B2L + o * B2_STR + 2 * k) = pk2lo(la, lb);
        }
    } else {
        __shared__ int h[NE];
        __shared__ int sflag;
        int b = blockIdx.x - NE;
        if (tid < NE) h[tid] = 0;
        int is64 = detect_is64(idxp, tid, &sflag);
        int e = get_idx(idxp, b * PTHREADS + tid, is64);
        atomicAdd(&h[e], 1);
        __syncthreads();
        if (tid < NE) g_hist[b][tid] = h[tid];
    }
}

// ---------------------------------------------------------------------------
// K1: fused scan + scatter + tile-list (NB=64 tiles, full first)
// ---------------------------------------------------------------------------
__global__ void finish_kernel(const void* idxp) {
    __shared__ int preS[NE], totS[NE], offS[NE];
    __shared__ int sflag;
    int t = threadIdx.x, b = blockIdx.x;
    int is64 = detect_is64(idxp, t, &sflag);
    if (t < NE) {
        int pre = 0, tot = 0;
        #pragma unroll 8
        for (int bb = 0; bb < NHB; bb++) {
            int v = g_hist[bb][t];
            tot += v;
            if (bb < b) pre += v;
        }
        preS[t] = pre; totS[t] = tot;
    }
    __syncthreads();
    if (t == 0) {
        int s = 0;
        for (int e2 = 0; e2 < NE; e2++) { offS[e2] = s; s += totS[e2]; }
    }
    __syncthreads();
    int my = b * PTHREADS + t;
    int e = get_idx(idxp, my, is64);
    int rank = atomicAdd(&preS[e], 1);
    g_perm[offS[e] + rank] = my;

    if (b == 0 && t == 0) {
        int ts = 0;
        for (int e2 = 0; e2 < NE; e2++) {
            int c = totS[e2], o = offS[e2], nf = c >> 6;
            for (int i = 0; i < nf; i++) {
                g_tile_e[ts] = e2; g_tile_r0[ts] = o + (i << 6); g_tile_R[ts] = NB; ts++;
            }
        }
        for (int e2 = 0; e2 < NE; e2++) {
            int c = totS[e2], o = offS[e2], nf = c >> 6, rem = c & 63;
            if (rem) {
                g_tile_e[ts] = e2; g_tile_r0[ts] = o + (nf << 6); g_tile_R[ts] = rem; ts++;
            }
        }
        g_ntiles = ts;
        g_tile_ctr = 0;
    }
}

// ---------------------------------------------------------------------------
// Compute: HMMA bf16 3-term split, M=64 tiles, 2 CTAs/SM, inline conversion
// SMEM: ctrl 1024 | sA 36864 (hi, lo at +18432) | sB images 63488 = 101376
// ---------------------------------------------------------------------------
#define A_OFF  1024
#define AHALF  18432
#define BB_OFF (1024 + 36864)
#define SMEM_BYTES (1024 + 36864 + 63488)

__device__ __forceinline__ uint32_t smem_u32(const void* p) {
    uint32_t a;
    asm("{ .reg .u64 t; cvta.to.shared.u64 t, %1; cvt.u32.u64 %0, t; }"
        : "=r"(a) : "l"(p));
    return a;
}
__device__ __forceinline__ void cpa16(uint32_t dst, const void* src) {
    asm volatile("cp.async.cg.shared.global [%0], [%1], 16;\n" :: "r"(dst), "l"(src));
}
__device__ __forceinline__ void cpa_commit() {
    asm volatile("cp.async.commit_group;\n" ::: "memory");
}
__device__ __forceinline__ void cpa_wait() {
    asm volatile("cp.async.wait_group 0;\n" ::: "memory");
}
__device__ __forceinline__ void ldm4(uint32_t* r, uint32_t a) {
    asm volatile("ldmatrix.sync.aligned.m8n8.x4.shared.b16 {%0,%1,%2,%3}, [%4];"
                 : "=r"(r[0]), "=r"(r[1]), "=r"(r[2]), "=r"(r[3]) : "r"(a));
}
__device__ __forceinline__ void ldm2(uint32_t* r, uint32_t a) {
    asm volatile("ldmatrix.sync.aligned.m8n8.x2.shared.b16 {%0,%1}, [%2];"
                 : "=r"(r[0]), "=r"(r[1]) : "r"(a));
}
__device__ __forceinline__ void mma16816(float* d, const uint32_t* a, const uint32_t* b) {
    asm volatile(
        "mma.sync.aligned.m16n8k16.row.col.f32.bf16.bf16.f32 "
        "{%0,%1,%2,%3}, {%4,%5,%6,%7}, {%8,%9}, {%0,%1,%2,%3};"
        : "+f"(d[0]), "+f"(d[1]), "+f"(d[2]), "+f"(d[3])
        : "r"(a[0]), "r"(a[1]), "r"(a[2]), "r"(a[3]), "r"(b[0]), "r"(b[1]));
}

__global__ void __launch_bounds__(NTHREADS, 2)
compute_kernel(const float* __restrict__ x, float* __restrict__ y)
{
    extern __shared__ unsigned char sm[];
    int* s_tile = (int*)(sm);
    int* s_node = (int*)(sm + 16);

    const int tid = threadIdx.x, lane = tid & 31, wid = tid >> 5;
    const int wr = wid & 3, wc = wid >> 2;        // 4 row stripes x 4 col groups
    const uint32_t base_u = smem_u32(sm);
    const uint32_t sA = base_u + A_OFF;
    const uint32_t sB = base_u + BB_OFF;
    const int nt = g_ntiles;

    // ldmatrix lane components (verified in R10/R11, rel_err 4.5e-6)
    const int a_row = lane & 15;
    const int a_k16 = (lane >> 4) << 4;
    const int b_row = (lane & 7) + ((lane >> 4) << 3);
    const int b_k16 = ((lane >> 3) & 1) << 4;
    const int b2_row = lane & 7;                       // x2: lanes 0..15 used
    const int b2_k16 = ((lane >> 3) & 1) << 4;

    for (int iter = 0; iter < 16; iter++) {
        if (tid == 0) *s_tile = atomicAdd(&g_tile_ctr, 1);
        __syncthreads();
        const int t = *s_tile;
        if (t >= nt) break;
        const int e  = g_tile_e[t];
        const int r0 = g_tile_r0[t];
        const int R  = g_tile_R[t];
        if (tid < NB) s_node[tid] = g_perm[r0 + min(tid, R - 1)];
        __syncthreads();

        // Issue B image staging, then convert seg0 A (independent) to hide it
        {
            const unsigned char* bs = g_Wimg + (size_t)e * IMG_BYTES;
            for (int i = tid; i < IMG_BYTES / 16; i += NTHREADS)
                cpa16(sB + 16u * i, bs + 16 * i);
            cpa_commit();
        }
        for (int i = tid; i < R * 48; i += NTHREADS) {
            int nb = i / 48, k = 2 * (i - 48 * nb);
            float2 v = *(const float2*)(x + (size_t)s_node[nb] * IN_SIZE + k);
            float la, lb;
            uint32_t h = pk2(v.x, v.y, &la, &lb);
            *(uint32_t*)(sm + A_OFF + nb * B0_STR + 2 * k) = h;
            *(uint32_t*)(sm + A_OFF + AHALF + nb * B0_STR + 2 * k) = pk2lo(la, lb);
        }
        cpa_wait();
        __syncthreads();

        // ===== seg0: M=64 N=96 K=96; col group = 24 (2 n8 via x4 + 1 via x2)
        if (16 * wr < R) {
            float c[3][4];
            #pragma unroll
            for (int j = 0; j < 3; j++)
                #pragma unroll
                for (int q = 0; q < 4; q++) c[j][q] = 0.f;
            const int cbase = 24 * wc;
            const uint32_t ah = sA + (16 * wr + a_row) * B0_STR + a_k16;
            const uint32_t al = ah + AHALF;
            const uint32_t bh4 = sB + OFF_B0H + (cbase + b_row) * B0_STR + b_k16;
            const uint32_t bl4 = sB + OFF_B0L + (cbase + b_row) * B0_STR + b_k16;
            const uint32_t bh2 = sB + OFF_B0H + (cbase + 16 + b2_row) * B0_STR + b2_k16;
            const uint32_t bl2 = sB + OFF_B0L + (cbase + 16 + b2_row) * B0_STR + b2_k16;
            #pragma unroll
            for (int kk = 0; kk < 6; kk++) {
                const int ko = 32 * kk;
                uint32_t A[4], Al[4], Bh[4], Bl[4], Bh2[2], Bl2[2];
                ldm4(A, ah + ko);  ldm4(Al, al + ko);
                ldm4(Bh, bh4 + ko); ldm4(Bl, bl4 + ko);
                ldm2(Bh2, bh2 + ko); ldm2(Bl2, bl2 + ko);
                mma16816(c[0], A, Bh);     mma16816(c[0], Al, Bh);
                mma16816(c[0], A, Bl);
                mma16816(c[1], A, Bh + 2); mma16816(c[1], Al, Bh + 2);
                mma16816(c[1], A, Bl + 2);
                mma16816(c[2], A, Bh2);    mma16816(c[2], Al, Bh2);
                mma16816(c[2], A, Bl2);
            }
            int rA = 16 * wr + (lane >> 2), rB = rA + 8;
            int cb = cbase + 2 * (lane & 3);
            if (rA < R) {
                float* yp = y + (size_t)s_node[rA] * OUT_SIZE;
                #pragma unroll
                for (int j = 0; j < 3; j++)
                    *(float2*)(yp + cb + 8 * j) = make_float2(c[j][0], c[j][1]);
            }
            if (rB < R) {
                float* yp = y + (size_t)s_node[rB] * OUT_SIZE;
                #pragma unroll
                for (int j = 0; j < 3; j++)
                    *(float2*)(yp + cb + 8 * j) = make_float2(c[j][2], c[j][3]);
            }
        }
        __syncthreads();

        // ===== seg1: 3 GEMMs (M=64 N=64 K=64), batched {0,1} then {2} =====
        for (int ph = 0; ph < 2; ph++) {
            const int mbase = 2 * ph;
            const int nm = (ph == 0) ? 2 : 1;
            for (int i = tid; i < nm * R * 32; i += NTHREADS) {
                int j = i / (R * 32), rem = i - j * (R * 32);
                int nb = rem / 32, k = 2 * (rem - 32 * nb);
                int m = mbase + j;
                const float* fr = x + (size_t)s_node[nb] * IN_SIZE + 96;
                float la, lb;
                uint32_t h = pk2(fr[3 * k + m], fr[3 * (k + 1) + m], &la, &lb);
                *(uint32_t*)(sm + A_OFF + j * 9216 + nb * B1_STR + 2 * k) = h;
                *(uint32_t*)(sm + A_OFF + AHALF + j * 9216 + nb * B1_STR + 2 * k) =
                    pk2lo(la, lb);
            }
            __syncthreads();
            if (16 * wr < R) {
                const uint32_t bh4 = sB + OFF_B1H + (16 * wc + b_row) * B1_STR + b_k16;
                const uint32_t bl4 = sB + OFF_B1L + (16 * wc + b_row) * B1_STR + b_k16;
                for (int j = 0; j < nm; j++) {
                    const int m = mbase + j;
                    float c[2][4];
                    #pragma unroll
                    for (int jj = 0; jj < 2; jj++)
                        #pragma unroll
                        for (int q = 0; q < 4; q++) c[jj][q] = 0.f;
                    const uint32_t ah = sA + j * 9216 + (16 * wr + a_row) * B1_STR + a_k16;
                    const uint32_t al = ah + AHALF;
                    #pragma unroll
                    for (int kk = 0; kk < 4; kk++) {
                        const int ko = 32 * kk;
                        uint32_t A[4], Al[4], Bh[4], Bl[4];
                        ldm4(A, ah + ko);  ldm4(Al, al + ko);
                        ldm4(Bh, bh4 + ko); ldm4(Bl, bl4 + ko);
                        mma16816(c[0], A, Bh);     mma16816(c[0], Al, Bh);
                        mma16816(c[0], A, Bl);
                        mma16816(c[1], A, Bh + 2); mma16816(c[1], Al, Bh + 2);
                        mma16816(c[1], A, Bl + 2);
                    }
                    int rA = 16 * wr + (lane >> 2), rB = rA + 8;
                    int cb = 16 * wc + 2 * (lane & 3);
                    if (rA < R) {
                        float* yp = y + (size_t)s_node[rA] * OUT_SIZE + 96 + m;
                        #pragma unroll
                        for (int jj = 0; jj < 2; jj++) {
                            yp[3 * (cb + 8 * jj)] = c[jj][0];
                            yp[3 * (cb + 8 * jj + 1)] = c[jj][1];
                        }
                    }
                    if (rB < R) {
                        float* yp = y + (size_t)s_node[rB] * OUT_SIZE + 96 + m;
                        #pragma unroll
                        for (int jj = 0; jj < 2; jj++) {
                            yp[3 * (cb + 8 * jj)] = c[jj][2];
                            yp[3 * (cb + 8 * jj + 1)] = c[jj][3];
                        }
                    }
                }
            }
            __syncthreads();
        }

        // ===== seg2: 5 GEMMs (M=64 N=32 K=32), batched {0,1,2} then {3,4} ==
        for (int ph = 0; ph < 2; ph++) {
            const int mbase = 3 * ph;
            const int nm = (ph == 0) ? 3 : 2;
            for (int i = tid; i < nm * R * 16; i += NTHREADS) {
                int j = i / (R * 16), rem = i - j * (R * 16);
                int nb = rem / 16, k = 2 * (rem - 16 * nb);
                int m = mbase + j;
                const float* fr = x + (size_t)s_node[nb] * IN_SIZE + 288;
                float la, lb;
                uint32_t h = pk2(fr[5 * k + m], fr[5 * (k + 1) + m], &la, &lb);
                *(uint32_t*)(sm + A_OFF + j * 5120 + nb * B2_STR + 2 * k) = h;
                *(uint32_t*)(sm + A_OFF + AHALF + j * 5120 + nb * B2_STR + 2 * k) =
                    pk2lo(la, lb);
            }
            __syncthreads();
            if (16 * wr < R) {
                const uint32_t bh2 = sB + OFF_B2H + (8 * wc + b2_row) * B2_STR + b2_k16;
                const uint32_t bl2 = sB + OFF_B2L + (8 * wc + b2_row) * B2_STR + b2_k16;
                for (int j = 0; j < nm; j++) {
                    const int m = mbase + j;
                    float c[4];
                    c[0] = c[1] = c[2] = c[3] = 0.f;
                    const uint32_t ah = sA + j * 5120 + (16 * wr + a_row) * B2_STR + a_k16;
                    const uint32_t al = ah + AHALF;
                    #pragma unroll
                    for (int kk = 0; kk < 2; kk++) {
                        const int ko = 32 * kk;
                        uint32_t A[4], Al[4], Bh2[2], Bl2[2];
                        ldm4(A, ah + ko);  ldm4(Al, al + ko);
                        ldm2(Bh2, bh2 + ko); ldm2(Bl2, bl2 + ko);
                        mma16816(c, A, Bh2);
                        mma16816(c, Al, Bh2);
                        mma16816(c, A, Bl2);
                    }
                    int rA = 16 * wr + (lane >> 2), rB = rA + 8;
                    int cb = 8 * wc + 2 * (lane & 3);
                    if (rA < R) {
                        float* yp = y + (size_t)s_node[rA] * OUT_SIZE + 288 + m;
                        yp[5 * cb] = c[0];
                        yp[5 * (cb + 1)] = c[1];
                    }
                    if (rB < R) {
                        float* yp = y + (size_t)s_node[rB] * OUT_SIZE + 288 + m;
                        yp[5 * cb] = c[2];
                        yp[5 * (cb + 1)] = c[3];
                    }
                }
            }
            __syncthreads();
        }
    }
}

// ---------------------------------------------------------------------------
// Launch (3 kernels)
// ---------------------------------------------------------------------------
extern "C" void kernel_launch(void* const* d_in, const int* in_sizes, int n_in,
                              void* d_out, int out_size)
{
    const float* W  = (const float*)d_in[0];   // [64, 14336]
    const float* x  = (const float*)d_in[1];   // [16384, 448]
    const void*  ix = d_in[2];                 // [16384] int32 or int64
    float* y = (float*)d_out;                  // [16384, 448]

    cudaFuncSetAttribute(compute_kernel,
                         cudaFuncAttributeMaxDynamicSharedMemorySize, SMEM_BYTES);

    prep_kernel<<<NE + NHB, PTHREADS>>>(W, ix);
    finish_kernel<<<NHB, PTHREADS>>>(ix);
    compute_kernel<<<GRID_COMPUTE, NTHREADS, SMEM_BYTES>>>(x, y);
}